// round 7
// baseline (speedup 1.0000x reference)
#include <cuda_runtime.h>
#include <cstdint>

// Problem constants
#define BB   2
#define SS   2048
#define DIM  2048
#define NH   16
#define KVH  4
#define HD   128
#define ROWS (BB*SS)          // 4096
#define QKVD 3072             // fused Q|K|V width
#define KOFF 2048
#define VOFF 2560

// ---------------------------------------------------------------------------
// Scratch (static device globals — no allocation)
// ---------------------------------------------------------------------------
__device__ float gXr [(size_t)ROWS * DIM];    // X, tf32, K-interleave16
__device__ float gWt [(size_t)QKVD * DIM];    // [Wq|Wk|Wv]^T, tf32, K-int16
__device__ float gWot[(size_t)DIM * DIM];     // Wo^T, tf32, K-int16
__device__ float gQKV[(size_t)ROWS * QKVD];   // Q,K d-permuted by rope; V normal
__device__ float gC  [(size_t)ROWS * DIM];    // attn ctx, tf32, K-int16

// ---------------------------------------------------------------------------
// helpers
// ---------------------------------------------------------------------------
__device__ __forceinline__ unsigned tf32u(float x) {
    unsigned u;
    asm("cvt.rna.tf32.f32 %0, %1;" : "=r"(u) : "f"(x));
    return u;
}
__device__ __forceinline__ float tf32f(float x) { return __uint_as_float(tf32u(x)); }
__device__ __forceinline__ float ex2(float x) {
    float r;
    asm("ex2.approx.ftz.f32 %0, %1;" : "=f"(r) : "f"(x));
    return r;
}

// K-interleave-16: P16(k) = (k&3)*4 + (k>>2)  (involution)
// out position p holds logical k = P16(p):
//   out f4#0 = {in0,in4,in8,in12}, f4#1 = y-comps, etc.
__global__ void permute_round_x(const float* __restrict__ in,
                                float* __restrict__ out) {
    int idx = blockIdx.x * blockDim.x + threadIdx.x;   // one 16-group
    if (idx >= ROWS * (DIM / 16)) return;
    const float4* s = (const float4*)(in + (size_t)idx * 16);
    float4 v0 = s[0], v1 = s[1], v2 = s[2], v3 = s[3];
    float4* d = (float4*)(out + (size_t)idx * 16);
    d[0] = make_float4(tf32f(v0.x), tf32f(v1.x), tf32f(v2.x), tf32f(v3.x));
    d[1] = make_float4(tf32f(v0.y), tf32f(v1.y), tf32f(v2.y), tf32f(v3.y));
    d[2] = make_float4(tf32f(v0.z), tf32f(v1.z), tf32f(v2.z), tf32f(v3.z));
    d[3] = make_float4(tf32f(v0.w), tf32f(v1.w), tf32f(v2.w), tf32f(v3.w));
}

// Transpose-pack all 4 weights: W[k][n] -> out[n][k int16-permuted], tf32.
// grid (64,64,4), block (32,8). z selects the weight.
__global__ void wpack_all(const float* __restrict__ wq,
                          const float* __restrict__ wk,
                          const float* __restrict__ wv,
                          const float* __restrict__ wo,
                          float* __restrict__ Wt, float* __restrict__ Wot) {
    const float* W;
    float* out;
    int Nw;
    int z = blockIdx.z;
    if (z == 0)      { W = wq; out = Wt;                         Nw = 2048; }
    else if (z == 1) { W = wo; out = Wot;                        Nw = 2048; }
    else if (z == 2) { W = wk; out = Wt + (size_t)2048 * 2048;   Nw = 512;  }
    else             { W = wv; out = Wt + (size_t)2560 * 2048;   Nw = 512;  }
    int n0 = blockIdx.x * 32;
    if (n0 >= Nw) return;

    __shared__ float t[32][33];
    int tx = threadIdx.x, ty = threadIdx.y;
    int k0 = blockIdx.y * 32;
    #pragma unroll
    for (int i = 0; i < 4; i++)
        t[ty + 8 * i][tx] = W[(size_t)(k0 + ty + 8 * i) * Nw + n0 + tx];
    __syncthreads();
    int grp = tx >> 4, pos = tx & 15;
    int ksrc = grp * 16 + (pos & 3) * 4 + (pos >> 2);   // P16
    #pragma unroll
    for (int i = 0; i < 4; i++)
        out[(size_t)(n0 + ty + 8 * i) * 2048 + k0 + tx] = tf32f(t[ksrc][ty + 8 * i]);
}

// ---------------------------------------------------------------------------
// TF32 GEMM v3: C[M,N] = A[M,K] @ Bt[N,K]^T, operands K-interleave16.
// 128x128 block, 4 warps (2x2), warp tile 64x64, BK=32, cp.async dbuf.
// All fragment loads are conflict-free LDS.128 (stride 48 ≡ 16 mod 32).
// ---------------------------------------------------------------------------
#define GST 48
#define GEMM2_SMEM (2 * 2 * 128 * GST * 4)   // 98304 B

__device__ __forceinline__ void cp16(unsigned dst, const void* src) {
    asm volatile("cp.async.cg.shared.global [%0], [%1], 16;\n"
                 :: "r"(dst), "l"(src));
}

__device__ __forceinline__ void mma8(float* c, const unsigned* a,
                                     unsigned b0, unsigned b1) {
    asm volatile(
        "mma.sync.aligned.m16n8k8.row.col.f32.tf32.tf32.f32 "
        "{%0,%1,%2,%3}, {%4,%5,%6,%7}, {%8,%9}, {%0,%1,%2,%3};\n"
        : "+f"(c[0]), "+f"(c[1]), "+f"(c[2]), "+f"(c[3])
        : "r"(a[0]), "r"(a[1]), "r"(a[2]), "r"(a[3]), "r"(b0), "r"(b1));
}

__global__ __launch_bounds__(128) void tf32_gemm3(
    const float* __restrict__ A, const float* __restrict__ Bt,
    float* __restrict__ C, int N, int K)
{
    extern __shared__ float sm[];
    float* As = sm;                    // [2][128][GST]
    float* Bs = sm + 2 * 128 * GST;    // [2][128][GST]

    const int tid  = threadIdx.x;
    const int lane = tid & 31;
    const int w    = tid >> 5;
    const int g    = lane >> 2;
    const int l    = lane & 3;
    const int wm   = (w >> 1) * 64;
    const int wn   = (w & 1) * 64;
    const long bm  = (long)blockIdx.y * 128;
    const long bn  = (long)blockIdx.x * 128;

    const unsigned sAu = (unsigned)__cvta_generic_to_shared(As);
    const unsigned sBu = (unsigned)__cvta_generic_to_shared(Bs);

    const int frow = tid >> 3;
    const int fcol = (tid & 7) << 2;
    const float* Abase = A  + (bm + frow) * K + fcol;
    const float* Bbase = Bt + (bn + frow) * K + fcol;

    float acc[4][8][4];
    #pragma unroll
    for (int mt = 0; mt < 4; mt++)
        #pragma unroll
        for (int nt = 0; nt < 8; nt++)
            #pragma unroll
            for (int j = 0; j < 4; j++) acc[mt][nt][j] = 0.f;

    const int niter = K / 32;

    auto issue = [&](int it, int buf) {
        long k0 = (long)it * 32;
        #pragma unroll
        for (int p = 0; p < 8; p++)
            cp16(sAu + (unsigned)(((buf * 128 + frow + p * 16) * GST + fcol) * 4),
                 Abase + (long)p * 16 * K + k0);
        #pragma unroll
        for (int p = 0; p < 8; p++)
            cp16(sBu + (unsigned)(((buf * 128 + frow + p * 16) * GST + fcol) * 4),
                 Bbase + (long)p * 16 * K + k0);
        asm volatile("cp.async.commit_group;\n");
    };

    issue(0, 0);

    for (int it = 0; it < niter; it++) {
        const int buf = it & 1;
        if (it + 1 < niter) {
            issue(it + 1, buf ^ 1);
            asm volatile("cp.async.wait_group 1;\n");
        } else {
            asm volatile("cp.async.wait_group 0;\n");
        }
        __syncthreads();

        const float* Ab = As + buf * 128 * GST;
        const float* Bb = Bs + buf * 128 * GST;

        #pragma unroll
        for (int kk = 0; kk < 2; kk++) {        // two k16 halves
            float4 a0[4], a1[4], bv[8];
            #pragma unroll
            for (int mt = 0; mt < 4; mt++) {
                a0[mt] = *(const float4*)&Ab[(wm + mt * 16 + g)     * GST + kk * 16 + 4 * l];
                a1[mt] = *(const float4*)&Ab[(wm + mt * 16 + g + 8) * GST + kk * 16 + 4 * l];
            }
            #pragma unroll
            for (int nt = 0; nt < 8; nt++)
                bv[nt] = *(const float4*)&Bb[(wn + nt * 8 + g) * GST + kk * 16 + 4 * l];

            #pragma unroll
            for (int mt = 0; mt < 4; mt++) {
                unsigned aA[4], aB[4];
                aA[0] = __float_as_uint(a0[mt].x); aA[1] = __float_as_uint(a1[mt].x);
                aA[2] = __float_as_uint(a0[mt].y); aA[3] = __float_as_uint(a1[mt].y);
                aB[0] = __float_as_uint(a0[mt].z); aB[1] = __float_as_uint(a1[mt].z);
                aB[2] = __float_as_uint(a0[mt].w); aB[3] = __float_as_uint(a1[mt].w);
                #pragma unroll
                for (int nt = 0; nt < 8; nt++) {
                    mma8(acc[mt][nt], aA,
                         __float_as_uint(bv[nt].x), __float_as_uint(bv[nt].y));
                    mma8(acc[mt][nt], aB,
                         __float_as_uint(bv[nt].z), __float_as_uint(bv[nt].w));
                }
            }
        }
        __syncthreads();
    }

    #pragma unroll
    for (int mt = 0; mt < 4; mt++)
        #pragma unroll
        for (int nt = 0; nt < 8; nt++) {
            const float* c = acc[mt][nt];
            long row = bm + wm + mt * 16 + g;
            long col = bn + wn + nt * 8 + 2 * l;
            *(float2*)&C[row * N + col]       = make_float2(c[0], c[1]);
            *(float2*)&C[(row + 8) * N + col] = make_float2(c[2], c[3]);
        }
}

// ---------------------------------------------------------------------------
// RoPE in-place on Q/K, emitting d-PERMUTED 8-group layout {0,4,1,5,2,6,3,7}.
// Each thread owns whole logical groups (t, t+8) -> race-free in-place.
// ---------------------------------------------------------------------------
__global__ void rope_kernel(float* __restrict__ x,
                            const float* __restrict__ cosT,
                            const float* __restrict__ sinT,
                            int nh_shift, int stride)
{
    int idx = blockIdx.x * blockDim.x + threadIdx.x;
    int nheads = 1 << nh_shift;
    int total = ROWS * nheads * 8;
    if (idx >= total) return;
    int t = idx & 7;
    int h = (idx >> 3) & (nheads - 1);
    int r = idx >> (3 + nh_shift);
    int s = r & (SS - 1);

    const float* cs = cosT + s * HD + 8 * t;
    const float* sn = sinT + s * HD + 8 * t;
    float* p = x + (size_t)r * stride + h * HD + 8 * t;

    float a[8], bv[8];
    *(float4*)(a)      = *(const float4*)(p);
    *(float4*)(a + 4)  = *(const float4*)(p + 4);
    *(float4*)(bv)     = *(const float4*)(p + 64);
    *(float4*)(bv + 4) = *(const float4*)(p + 68);

    float oa[8], ob[8];
    #pragma unroll
    for (int j = 0; j < 8; j++) {
        float c0 = cs[j],      s0 = sn[j];
        float c1 = cs[64 + j], s1 = sn[64 + j];
        oa[j] = a[j] * c0 - bv[j] * s0;
        ob[j] = bv[j] * c1 + a[j] * s1;
    }
    float wa[8], wb[8];
    #pragma unroll
    for (int j = 0; j < 4; j++) {
        wa[2 * j] = oa[j];  wa[2 * j + 1] = oa[j + 4];
        wb[2 * j] = ob[j];  wb[2 * j + 1] = ob[j + 4];
    }
    *(float4*)(p)      = *(float4*)(wa);
    *(float4*)(p + 4)  = *(float4*)(wa + 4);
    *(float4*)(p + 64) = *(float4*)(wb);
    *(float4*)(p + 68) = *(float4*)(wb + 4);
}

// ---------------------------------------------------------------------------
// Tensor-core flash attention (R3 shape: 64 q-rows, 4 warps, 64-key tiles).
// Q/K d-permuted -> all QK fragments are conflict-free LDS.64 (stride 136).
// Epilogue writes ctx in K-interleave16 layout for the Wo GEMM.
// ---------------------------------------------------------------------------
#define KST 136
#define VST 136
#define PST 68
#define ATTN_SMEM ((64*KST + 64*VST + 64*PST) * 4)   // 87040 B

__global__ __launch_bounds__(128) void attn_mma(
    const float* __restrict__ QKVg, const float* __restrict__ alibi,
    const float* __restrict__ amask, float* __restrict__ Og)
{
    extern __shared__ float smn[];
    float* sK = smn;              // [64][136]
    float* sV = smn + 64 * KST;   // [64][136]
    float* sP = sV + 64 * VST;    // [64][68]
    float* sQ = smn;              // alias (temp, consumed before loop)

    const int tid  = threadIdx.x;
    const int lane = tid & 31;
    const int w    = tid >> 5;
    const int g    = lane >> 2;
    const int l    = lane & 3;
    const int bh   = blockIdx.y;
    const int b    = bh >> 4;
    const int h    = bh & 15;
    const int kvh  = h >> 2;
    const int bxr  = gridDim.x - 1 - blockIdx.x;   // heavy blocks first
    const int q0   = bxr * 64;
    const int ktiles = bxr + 1;

    for (int i = tid; i < 64 * 32; i += 128) {
        int r = i >> 5, c4 = (i & 31) << 2;
        *(float4*)&sQ[r * KST + c4] =
            *(const float4*)&QKVg[(size_t)(b * SS + q0 + r) * QKVD + h * HD + c4];
    }
    __syncthreads();

    unsigned qf[16][4];
    #pragma unroll
    for (int kc = 0; kc < 16; kc++) {
        float2 q0v = *(const float2*)&sQ[(w * 16 + g)     * KST + kc * 8 + 2 * l];
        float2 q1v = *(const float2*)&sQ[(w * 16 + g + 8) * KST + kc * 8 + 2 * l];
        qf[kc][0] = tf32u(q0v.x);
        qf[kc][1] = tf32u(q1v.x);
        qf[kc][2] = tf32u(q0v.y);
        qf[kc][3] = tf32u(q1v.y);
    }
    __syncthreads();

    const float L2E = 1.4426950408889634f;
    const float SCL = 0.08838834764831845f * L2E;

    float m0 = -1e30f, m1 = -1e30f, s0 = 0.f, s1 = 0.f;
    float o[16][4];
    #pragma unroll
    for (int i = 0; i < 16; i++)
        #pragma unroll
        for (int j = 0; j < 4; j++) o[i][j] = 0.f;

    const int qrow = q0 + w * 16 + g;

    for (int kt = 0; kt < ktiles; kt++) {
        const int k0 = kt * 64;

        for (int i = tid; i < 64 * 32; i += 128) {
            int r = i >> 5, c4 = (i & 31) << 2;
            size_t rowbase = (size_t)(b * SS + k0 + r) * QKVD + kvh * HD + c4;
            float4 kv = *(const float4*)&QKVg[rowbase + KOFF];
            kv.x = tf32f(kv.x); kv.y = tf32f(kv.y);
            kv.z = tf32f(kv.z); kv.w = tf32f(kv.w);
            *(float4*)&sK[r * KST + c4] = kv;
            float4 vv = *(const float4*)&QKVg[rowbase + VOFF];
            vv.x = tf32f(vv.x); vv.y = tf32f(vv.y);
            vv.z = tf32f(vv.z); vv.w = tf32f(vv.w);
            *(float4*)&sV[r * VST + c4] = vv;
        }
        __syncthreads();

        float sc[8][4];
        #pragma unroll
        for (int nb = 0; nb < 8; nb++)
            #pragma unroll
            for (int j = 0; j < 4; j++) sc[nb][j] = 0.f;

        #pragma unroll
        for (int kc = 0; kc < 16; kc++) {
            #pragma unroll
            for (int nb = 0; nb < 8; nb++) {
                float2 kv2 = *(const float2*)&sK[(nb * 8 + g) * KST + kc * 8 + 2 * l];
                mma8(sc[nb], qf[kc],
                     __float_as_uint(kv2.x), __float_as_uint(kv2.y));
            }
        }

        const bool diag = (k0 == q0);
        float mx0 = -1e30f, mx1 = -1e30f;
        {
            const float* alr = &alibi[((size_t)b * SS + qrow) * SS + k0 + 2 * l];
            const float* amr = &amask[b * SS + k0 + 2 * l];
            #pragma unroll
            for (int nb = 0; nb < 8; nb++) {
                float2 amv = *(const float2*)(amr + nb * 8);
                float2 al0 = *(const float2*)(alr + nb * 8);
                float2 al1 = *(const float2*)(alr + nb * 8 + 8 * SS);
                sc[nb][0] = sc[nb][0] * SCL + (al0.x + amv.x) * L2E;
                sc[nb][1] = sc[nb][1] * SCL + (al0.y + amv.y) * L2E;
                sc[nb][2] = sc[nb][2] * SCL + (al1.x + amv.x) * L2E;
                sc[nb][3] = sc[nb][3] * SCL + (al1.y + amv.y) * L2E;
                if (diag) {
                    int kc0 = k0 + nb * 8 + 2 * l;
                    if (kc0     > qrow)     sc[nb][0] = -1e9f;
                    if (kc0 + 1 > qrow)     sc[nb][1] = -1e9f;
                    if (kc0     > qrow + 8) sc[nb][2] = -1e9f;
                    if (kc0 + 1 > qrow + 8) sc[nb][3] = -1e9f;
                }
                mx0 = fmaxf(mx0, fmaxf(sc[nb][0], sc[nb][1]));
                mx1 = fmaxf(mx1, fmaxf(sc[nb][2], sc[nb][3]));
            }
        }

        mx0 = fmaxf(mx0, __shfl_xor_sync(0xffffffffu, mx0, 1));
        mx0 = fmaxf(mx0, __shfl_xor_sync(0xffffffffu, mx0, 2));
        mx1 = fmaxf(mx1, __shfl_xor_sync(0xffffffffu, mx1, 1));
        mx1 = fmaxf(mx1, __shfl_xor_sync(0xffffffffu, mx1, 2));

        float mn0 = fmaxf(m0, mx0), mn1 = fmaxf(m1, mx1);
        float c0 = ex2(m0 - mn0), c1 = ex2(m1 - mn1);
        m0 = mn0; m1 = mn1;

        float rs0 = 0.f, rs1 = 0.f;
        #pragma unroll
        for (int nb = 0; nb < 8; nb++) {
            float p00 = ex2(sc[nb][0] - m0);
            float p01 = ex2(sc[nb][1] - m0);
            float p10 = ex2(sc[nb][2] - m1);
            float p11 = ex2(sc[nb][3] - m1);
            rs0 += p00 + p01;
            rs1 += p10 + p11;
            *(float2*)&sP[(w * 16 + g)     * PST + nb * 8 + 2 * l] =
                make_float2(tf32f(p00), tf32f(p01));
            *(float2*)&sP[(w * 16 + g + 8) * PST + nb * 8 + 2 * l] =
                make_float2(tf32f(p10), tf32f(p11));
        }
        rs0 += __shfl_xor_sync(0xffffffffu, rs0, 1);
        rs0 += __shfl_xor_sync(0xffffffffu, rs0, 2);
        rs1 += __shfl_xor_sync(0xffffffffu, rs1, 1);
        rs1 += __shfl_xor_sync(0xffffffffu, rs1, 2);
        s0 = s0 * c0 + rs0;
        s1 = s1 * c1 + rs1;

        #pragma unroll
        for (int nb = 0; nb < 16; nb++) {
            o[nb][0] *= c0; o[nb][1] *= c0;
            o[nb][2] *= c1; o[nb][3] *= c1;
        }
        __syncwarp();

        #pragma unroll
        for (int kc = 0; kc < 8; kc++) {
            unsigned a[4];
            a[0] = __float_as_uint(sP[(w * 16 + g)     * PST + kc * 8 + l]);
            a[1] = __float_as_uint(sP[(w * 16 + g + 8) * PST + kc * 8 + l]);
            a[2] = __float_as_uint(sP[(w * 16 + g)     * PST + kc * 8 + l + 4]);
            a[3] = __float_as_uint(sP[(w * 16 + g + 8) * PST + kc * 8 + l + 4]);
            #pragma unroll
            for (int nb = 0; nb < 16; nb++) {
                unsigned b0 = __float_as_uint(sV[(kc * 8 + l)     * VST + nb * 8 + g]);
                unsigned b1 = __float_as_uint(sV[(kc * 8 + l + 4) * VST + nb * 8 + g]);
                mma8(o[nb], a, b0, b1);
            }
        }
        __syncthreads();
    }

    // epilogue: O /= l, tf32-round, write K-INTERLEAVE16 ctx for Wo GEMM.
    // Thread holds cols j16 = 8*(nb&1) + 2l (+1) of 16-group (nb>>1);
    // P16 positions: pos0 = 8*(l&1) + 2*(nb&1) + (l>>1), pos1 = pos0 + 4.
    float inv0 = 1.0f / s0, inv1 = 1.0f / s1;
    size_t row0 = (size_t)(b * SS + qrow);
    #pragma unroll
    for (int nb = 0; nb < 16; nb++) {
        size_t cb = h * HD + (nb >> 1) * 16;
        int pos0 = 8 * (l & 1) + 2 * (nb & 1) + (l >> 1);
        Og[row0 * DIM + cb + pos0]           = tf32f(o[nb][0] * inv0);
        Og[row0 * DIM + cb + pos0 + 4]       = tf32f(o[nb][1] * inv0);
        Og[(row0 + 8) * DIM + cb + pos0]     = tf32f(o[nb][2] * inv1);
        Og[(row0 + 8) * DIM + cb + pos0 + 4] = tf32f(o[nb][3] * inv1);
    }
}

// ---------------------------------------------------------------------------
// Launch
// ---------------------------------------------------------------------------
extern "C" void kernel_launch(void* const* d_in, const int* in_sizes, int n_in,
                              void* d_out, int out_size)
{
    const float* X     = (const float*)d_in[0];
    const float* cosT  = (const float*)d_in[1];
    const float* sinT  = (const float*)d_in[2];
    const float* alibi = (const float*)d_in[3];
    const float* amask = (const float*)d_in[4];
    const float* wq    = (const float*)d_in[5];
    const float* wk    = (const float*)d_in[6];
    const float* wv    = (const float*)d_in[7];
    const float* wo    = (const float*)d_in[8];
    float* out = (float*)d_out;

    float *Xr, *Wt, *Wot, *QKV, *C;
    cudaGetSymbolAddress((void**)&Xr,  gXr);
    cudaGetSymbolAddress((void**)&Wt,  gWt);
    cudaGetSymbolAddress((void**)&Wot, gWot);
    cudaGetSymbolAddress((void**)&QKV, gQKV);
    cudaGetSymbolAddress((void**)&C,   gC);

    cudaFuncSetAttribute(tf32_gemm3,
                         cudaFuncAttributeMaxDynamicSharedMemorySize, GEMM2_SMEM);
    cudaFuncSetAttribute(attn_mma,
                         cudaFuncAttributeMaxDynamicSharedMemorySize, ATTN_SMEM);

    permute_round_x<<<ROWS * (DIM / 16) / 256, 256>>>(X, Xr);
    wpack_all<<<dim3(64, 64, 4), dim3(32, 8)>>>(wq, wk, wv, wo, Wt, Wot);

    tf32_gemm3<<<dim3(QKVD / 128, ROWS / 128), 128, GEMM2_SMEM>>>(
        Xr, Wt, QKV, QKVD, DIM);

    rope_kernel<<<(ROWS * NH * 8 + 255) / 256, 256>>>(QKV, cosT, sinT, 4, QKVD);
    rope_kernel<<<(ROWS * KVH * 8 + 255) / 256, 256>>>(QKV + KOFF, cosT, sinT, 2, QKVD);

    attn_mma<<<dim3(SS / 64, BB * NH), 128, ATTN_SMEM>>>(QKV, alibi, amask, C);

    tf32_gemm3<<<dim3(DIM / 128, ROWS / 128), 128, GEMM2_SMEM>>>(
        C, Wot, out, DIM, DIM);
}